// round 6
// baseline (speedup 1.0000x reference)
#include <cuda_runtime.h>
#include <math_constants.h>

#define BB 512
#define TT 512
#define KK 64

// 16.7 MB history scratch (argmax index per (b, t, j)), plus per-batch best-last tag.
__device__ unsigned char g_hist[(size_t)BB * TT * KK];
__device__ int g_best[BB];

// ---------------------------------------------------------------------------
// Forward Viterbi, one WARP per batch (no __syncthreads in the time loop).
//   Lane l owns next-tags j0 = l and j1 = l + 32. Scores in registers,
//   broadcast via shfl. Live prev-tag set kept as two 32-bit ballot masks.
//   Exact pruning: i is prunable iff s_i < smax + (Tmin - Tmax) - 0.05; the
//   0.05 margin >> float rounding (<= ~5e-4 at |s|~1500), so a pruned i can
//   never be the argmax, not even via ties. Survivors iterated in ascending i
//   (ffs over mask0 then mask1) with strict '>', exactly matching jnp.argmax
//   first-occurrence semantics.
// ---------------------------------------------------------------------------
__global__ __launch_bounds__(128) void viterbi_forward(
    const float* __restrict__ emissions,   // [B, T, K]
    const int*   __restrict__ mask,        // [B, T]
    const float* __restrict__ start_t,     // [K]
    const float* __restrict__ end_t,       // [K]
    const float* __restrict__ trans)       // [K, K]
{
    const int tid  = threadIdx.x;
    const int lane = tid & 31;
    const int w    = tid >> 5;
    const int b    = blockIdx.x * 4 + w;

    // trans pair layout: tp_sh[i][l] = (trans[i][l], trans[i][l+32])
    __shared__ __align__(16) float2 tp_sh[KK][32];
    __shared__ float red_sh[8];

    // ---- one-time: stage trans, compute global Tmin/Tmax ----
    float tmn = CUDART_INF_F, tmx = -CUDART_INF_F;
    for (int i = w; i < KK; i += 4) {
        const float a = trans[i * KK + lane];
        const float c = trans[i * KK + 32 + lane];
        tp_sh[i][lane] = make_float2(a, c);
        tmn = fminf(tmn, fminf(a, c));
        tmx = fmaxf(tmx, fmaxf(a, c));
    }
#pragma unroll
    for (int d = 16; d; d >>= 1) {
        tmn = fminf(tmn, __shfl_xor_sync(0xFFFFFFFFu, tmn, d));
        tmx = fmaxf(tmx, __shfl_xor_sync(0xFFFFFFFFu, tmx, d));
    }
    if (lane == 0) { red_sh[w] = tmn; red_sh[4 + w] = tmx; }
    __syncthreads();
    const float mn = fminf(fminf(red_sh[0], red_sh[1]), fminf(red_sh[2], red_sh[3]));
    const float mx = fmaxf(fmaxf(red_sh[4], red_sh[5]), fmaxf(red_sh[6], red_sh[7]));
    const float thrD = (mn - mx) - 0.05f;

    const float* em = emissions + (size_t)b * TT * KK;
    const int*   mk = mask + (size_t)b * TT;

    // ---- init scores (t = 0) ----
    float s0 = start_t[lane]      + em[lane];
    float s1 = start_t[lane + 32] + em[lane + 32];

    // ---- initial live masks ----
    unsigned mask0, mask1;
    {
        float mm = fmaxf(s0, s1);
#pragma unroll
        for (int d = 16; d; d >>= 1)
            mm = fmaxf(mm, __shfl_xor_sync(0xFFFFFFFFu, mm, d));
        const float thr = mm + thrD;
        mask0 = __ballot_sync(0xFFFFFFFFu, s0 >= thr);
        mask1 = __ballot_sync(0xFFFFFFFFu, s1 >= thr);
    }

    // ---- prefetch (depth 2): emissions + mask ----
    float e0c = em[KK + lane],      e1c = em[KK + 32 + lane];
    float e0n = em[2 * KK + lane],  e1n = em[2 * KK + 32 + lane];
    int   mc  = mk[1];
    int   mnx = mk[2];

    unsigned char* hp = g_hist + ((size_t)b * TT + 1) * KK;

    for (int t = 1; t < TT; ++t) {
        // branch-free prefetch of step t+2 (clamped at tail)
        const int tpf = (t + 2 < TT) ? (t + 2) : (TT - 1);
        const float e0p = em[tpf * KK + lane];
        const float e1p = em[tpf * KK + 32 + lane];
        const int   mpf = mk[tpf];

        // ---- phase A: argmax over live prev-tags (ascending, strict >) ----
        float bst0 = -CUDART_INF_F, bst1 = -CUDART_INF_F;
        int   bid0 = 0, bid1 = 0;

        unsigned m0 = mask0;            // uniform across warp (ballot)
        while (m0) {
            const int i = __ffs(m0) - 1;
            m0 &= m0 - 1;
            const float  si = __shfl_sync(0xFFFFFFFFu, s0, i);
            const float2 tp = tp_sh[i][lane];
            const float v0 = (si + tp.x) + e0c;
            const float v1 = (si + tp.y) + e1c;
            if (v0 > bst0) { bst0 = v0; bid0 = i; }
            if (v1 > bst1) { bst1 = v1; bid1 = i; }
        }
        unsigned m1 = mask1;
        while (m1) {
            const int i = __ffs(m1) - 1;
            m1 &= m1 - 1;
            const float  si = __shfl_sync(0xFFFFFFFFu, s1, i);
            const float2 tp = tp_sh[i + 32][lane];
            const float v0 = (si + tp.x) + e0c;
            const float v1 = (si + tp.y) + e1c;
            if (v0 > bst0) { bst0 = v0; bid0 = i + 32; }
            if (v1 > bst1) { bst1 = v1; bid1 = i + 32; }
        }

        // history always records the argmax; mask only gates the score.
        hp[lane]      = (unsigned char)bid0;
        hp[lane + 32] = (unsigned char)bid1;

        s0 = mc ? bst0 : s0;
        s1 = mc ? bst1 : s1;

        // ---- threshold + live masks for next step ----
        float mm = fmaxf(s0, s1);
#pragma unroll
        for (int d = 16; d; d >>= 1)
            mm = fmaxf(mm, __shfl_xor_sync(0xFFFFFFFFu, mm, d));
        const float thr = mm + thrD;
        mask0 = __ballot_sync(0xFFFFFFFFu, s0 >= thr);
        mask1 = __ballot_sync(0xFFFFFFFFu, s1 >= thr);

        hp += KK;
        e0c = e0n; e1c = e1n; e0n = e0p; e1n = e1p;
        mc  = mnx; mnx = mpf;
    }

    // ---- final: + end_transitions, first-index argmax over all 64 tags ----
    {
        const float v0 = s0 + end_t[lane];
        const float v1 = s1 + end_t[lane + 32];
        float bv; int bi;
        if (v1 > v0) { bv = v1; bi = lane + 32; }
        else         { bv = v0; bi = lane; }
#pragma unroll
        for (int d = 16; d; d >>= 1) {
            const float vo = __shfl_xor_sync(0xFFFFFFFFu, bv, d);
            const int   io = __shfl_xor_sync(0xFFFFFFFFu, bi, d);
            if (vo > bv || (vo == bv && io < bi)) { bv = vo; bi = io; }
        }
        if (lane == 0) g_best[b] = bi;
    }
}

// ---------------------------------------------------------------------------
// Backtrace: one block per batch. Stage the 32KB history slab + mask into
// shared, then one thread walks the dependent chain at LDS latency.
// Output tags written as FLOAT32 (harness output dtype).
// ---------------------------------------------------------------------------
__global__ __launch_bounds__(256) void viterbi_backtrace(
    const int*  __restrict__ mask,   // [B, T]
    float*      __restrict__ out)    // [B, T] float32 tags
{
    const int b = blockIdx.x;
    __shared__ unsigned char h[TT * KK];   // 32 KB
    __shared__ int msk[TT];                // 2 KB

    const uint4* src = (const uint4*)(g_hist + (size_t)b * TT * KK);
    uint4* dst = (uint4*)h;
#pragma unroll 4
    for (int k = threadIdx.x; k < (TT * KK) / 16; k += blockDim.x)
        dst[k] = src[k];
    for (int t = threadIdx.x; t < TT; t += blockDim.x)
        msk[t] = mask[b * TT + t];
    __syncthreads();

    if (threadIdx.x == 0) {
        int tag = g_best[b];
        out[b * TT + (TT - 1)] = (float)tag;
        for (int t = TT - 1; t >= 1; --t) {
            const int prev = h[t * KK + tag];
            tag = msk[t] ? prev : tag;
            out[b * TT + t - 1] = (float)tag;
        }
    }
}

extern "C" void kernel_launch(void* const* d_in, const int* in_sizes, int n_in,
                              void* d_out, int out_size)
{
    // Bind inputs by element count:
    //   16777216 -> emissions, 262144 -> attn_mask, 4096 -> transitions,
    //   64 -> start_transitions (first), end_transitions (second)
    const float* emissions = nullptr;
    const int*   attn_mask = nullptr;
    const float* start_t   = nullptr;
    const float* end_t     = nullptr;
    const float* trans     = nullptr;

    for (int i = 0; i < n_in; ++i) {
        const int sz = in_sizes[i];
        if (sz == BB * TT * KK)      emissions = (const float*)d_in[i];
        else if (sz == BB * TT)      attn_mask = (const int*)d_in[i];
        else if (sz == KK * KK)      trans     = (const float*)d_in[i];
        else if (sz == KK) {
            if (!start_t) start_t = (const float*)d_in[i];
            else          end_t   = (const float*)d_in[i];
        }
    }

    float* out = (float*)d_out;  // [512,512] float32 tag values

    viterbi_forward<<<BB / 4, 128>>>(emissions, attn_mask, start_t, end_t, trans);
    viterbi_backtrace<<<BB, 256>>>(attn_mask, out);
}